// round 17
// baseline (speedup 1.0000x reference)
#include <cuda_runtime.h>
#include <cuda_fp16.h>
#include <cuda_bf16.h>
#include <math.h>

// ---------------------------------------------------------------------------
// Problem constants
// ---------------------------------------------------------------------------
#define LQ      8160
#define DMODEL  256

__constant__ int c_lstart[4] = {0, 6144, 7680, 8064};

typedef unsigned int uint;

// ---------------------------------------------------------------------------
// Scratch (device globals; no allocation allowed)
// All GEMM operands packed as fp16 pairs (uint = __half2).
// A-side layout: [row][kp], kp = k/2. B-side: [kp][n].
// ---------------------------------------------------------------------------
__device__ uint g_qf16[LQ * 128];
__device__ uint g_if16[LQ * 128];
__device__ uint g_of16[LQ * 128];
__device__ uint g_Wsf [128 * 256];
__device__ uint g_Wtsf[128 * 256];
__device__ uint g_Wvf [128 * 256];
__device__ uint g_Wof [128 * 256];
__device__ uint g_Waf [128 * 128];
__device__ uint g_Wtaf[128 * 128];

__device__ float  g_proj   [LQ * 768];
__device__ __half g_value_h[LQ * DMODEL];

// ---------------------------------------------------------------------------
// helpers
// ---------------------------------------------------------------------------
__device__ __forceinline__ uint pack2h(float x, float y)
{
    __half2 t = __floats2half2_rn(x, y);
    return *reinterpret_cast<uint*>(&t);
}

__device__ __forceinline__ void mma_fp16(float* d, const uint* a, const uint* b)
{
    asm volatile(
        "mma.sync.aligned.m16n8k16.row.col.f32.f16.f16.f32 "
        "{%0,%1,%2,%3}, {%4,%5,%6,%7}, {%8,%9}, {%0,%1,%2,%3};"
        : "+f"(d[0]), "+f"(d[1]), "+f"(d[2]), "+f"(d[3])
        : "r"(a[0]), "r"(a[1]), "r"(a[2]), "r"(a[3]),
          "r"(b[0]), "r"(b[1]));
}

__device__ __forceinline__ void cpa16(void* dst_smem, const void* src, bool valid)
{
    uint ds = (uint)__cvta_generic_to_shared(dst_smem);
    int sz = valid ? 16 : 0;
    asm volatile("cp.async.cg.shared.global [%0], [%1], 16, %2;"
                 :: "r"(ds), "l"(src), "r"(sz));
}
#define CPA_COMMIT()  asm volatile("cp.async.commit_group;")
#define CPA_WAIT(n)   asm volatile("cp.async.wait_group %0;" :: "n"(n))

// ---------------------------------------------------------------------------
// Prep kernel: fp32 -> packed fp16, 4 output words (16 B) per thread.
// ---------------------------------------------------------------------------
__global__ __launch_bounds__(256) void prep_kernel(
    const float* __restrict__ query, const float* __restrict__ inp,
    const float* __restrict__ Ws,  const float* __restrict__ Wa,
    const float* __restrict__ Wts, const float* __restrict__ Wta,
    const float* __restrict__ Wv,  const float* __restrict__ Wo)
{
    const int b = blockIdx.x;
    const int tid = threadIdx.x;

    if (b < 2040) {                     // A-side
        const bool isQ = (b < 1020);
        const int  wb  = ((isQ ? b : b - 1020) * 256 + tid) * 4;
        const int  r   = wb >> 7;
        const int  kp  = wb & 127;
        const float* src = (isQ ? query : inp) + (size_t)r * 256 + 2 * kp;
        const float4 f0 = *(const float4*)(src);
        const float4 f1 = *(const float4*)(src + 4);
        uint4 o;
        o.x = pack2h(f0.x, f0.y); o.y = pack2h(f0.z, f0.w);
        o.z = pack2h(f1.x, f1.y); o.w = pack2h(f1.z, f1.w);
        *(uint4*)&(isQ ? g_qf16 : g_if16)[wb] = o;
    } else {                            // B-side weights
        const int u = b - 2040;
        const float* src; uint* df; int N; int bl;
        if      (u < 32)  { src = Ws;  df = g_Wsf;  N = 256; bl = u; }
        else if (u < 64)  { src = Wts; df = g_Wtsf; N = 256; bl = u - 32; }
        else if (u < 96)  { src = Wv;  df = g_Wvf;  N = 256; bl = u - 64; }
        else if (u < 128) { src = Wo;  df = g_Wof;  N = 256; bl = u - 96; }
        else if (u < 144) { src = Wa;  df = g_Waf;  N = 128; bl = u - 128; }
        else              { src = Wta; df = g_Wtaf; N = 128; bl = u - 144; }
        const int wb = (bl * 256 + tid) * 4;
        const int kp = wb / N;
        const int n  = wb - kp * N;
        const float4 r0 = *(const float4*)(src + (size_t)(2 * kp)     * N + n);
        const float4 r1 = *(const float4*)(src + (size_t)(2 * kp + 1) * N + n);
        uint4 o;
        o.x = pack2h(r0.x, r1.x); o.y = pack2h(r0.y, r1.y);
        o.z = pack2h(r0.z, r1.z); o.w = pack2h(r0.w, r1.w);
        *(uint4*)&df[wb] = o;
    }
}

// ---------------------------------------------------------------------------
// fp16 single-pass GEMM tile, templated on BM (64/128).
// 3-stage cp.async ring, ONE __syncthreads per K-chunk.
// ---------------------------------------------------------------------------
template<int BM>
struct GemmSmemH {
    uint A[BM][20];
    uint B[16][136];
};

template<int BM, typename OutT>
__device__ __forceinline__ void gemm_mma1(
    const uint* __restrict__ Ag,
    const uint* __restrict__ Bg, int ldbw,
    const float* __restrict__ bias,
    OutT* __restrict__ C, int ldc,
    int mt)
{
    constexpr int NT = (BM == 128) ? 8 : 4;
    constexpr int ALOOP = BM / 64;
    extern __shared__ char smem_raw[];
    GemmSmemH<BM>* bufs = reinterpret_cast<GemmSmemH<BM>*>(smem_raw);

    const int tid  = threadIdx.x;
    const int wid  = tid >> 5;
    const int lane = tid & 31;
    const int g    = lane >> 2;
    const int cq   = lane & 3;
    const int wm   = (BM == 128) ? (wid >> 1) : (wid >> 2);
    const int wn   = (BM == 128) ? (wid & 1)  : (wid & 3);

    const int bPair = tid >> 4;
    const int bN0   = (tid & 15) * 8;

    float acc[2][NT][4];
    #pragma unroll
    for (int i = 0; i < 2; i++)
        #pragma unroll
        for (int j = 0; j < NT; j++)
            #pragma unroll
            for (int v = 0; v < 4; v++) acc[i][j][v] = 0.f;

    auto issue = [&](int ck, int bsel) {
        GemmSmemH<BM>& s = bufs[bsel];
        #pragma unroll
        for (int i = 0; i < ALOOP; i++) {
            const int op  = i * 256 + tid;
            const int row = op >> 2;
            const int wq  = (op & 3) * 4;
            const int gr  = mt * BM + row;
            const bool v  = gr < LQ;
            const size_t base = (size_t)(v ? gr : 0) * 128 + ck * 16 + wq;
            cpa16(&s.A[row][wq], Ag + base, v);
        }
        const uint* bp = Bg + (size_t)(ck * 16 + bPair) * ldbw + bN0;
        cpa16(&s.B[bPair][bN0],     bp,     true);
        cpa16(&s.B[bPair][bN0 + 4], bp + 4, true);
        CPA_COMMIT();
    };

    issue(0, 0);
    issue(1, 1);

    for (int ck = 0; ck < 8; ck++) {
        if (ck < 7) { CPA_WAIT(1); }
        else        { CPA_WAIT(0); }
        __syncthreads();

        GemmSmemH<BM>& s = bufs[ck % 3];
        #pragma unroll
        for (int kt = 0; kt < 2; kt++) {
            uint af[2][4];
            #pragma unroll
            for (int m2 = 0; m2 < 2; m2++) {
                const int r  = wm * 32 + m2 * 16 + g;
                const int wc = 8 * kt + cq;
                af[m2][0] = s.A[r][wc];     af[m2][1] = s.A[r + 8][wc];
                af[m2][2] = s.A[r][wc + 4]; af[m2][3] = s.A[r + 8][wc + 4];
            }
            #pragma unroll
            for (int nt = 0; nt < NT; nt++) {
                const int n = wn * (NT * 8) + nt * 8 + g;
                uint bf[2];
                bf[0] = s.B[8 * kt + cq][n];
                bf[1] = s.B[8 * kt + cq + 4][n];
                #pragma unroll
                for (int m2 = 0; m2 < 2; m2++)
                    mma_fp16(acc[m2][nt], af[m2], bf);
            }
        }

        if (ck + 2 < 8) issue(ck + 2, (ck + 2) % 3);
    }

    #pragma unroll
    for (int m2 = 0; m2 < 2; m2++) {
        const int r0 = mt * BM + wm * 32 + m2 * 16 + g;
        const int r1 = r0 + 8;
        #pragma unroll
        for (int nt = 0; nt < NT; nt++) {
            const int cb = wn * (NT * 8) + nt * 8 + 2 * cq;
            const float b0 = bias[cb], b1 = bias[cb + 1];
            if (r0 < LQ) {
                C[(size_t)r0 * ldc + cb]     = (OutT)(acc[m2][nt][0] + b0);
                C[(size_t)r0 * ldc + cb + 1] = (OutT)(acc[m2][nt][1] + b1);
            }
            if (r1 < LQ) {
                C[(size_t)r1 * ldc + cb]     = (OutT)(acc[m2][nt][2] + b0);
                C[(size_t)r1 * ldc + cb + 1] = (OutT)(acc[m2][nt][3] + b1);
            }
        }
    }
}

// ---------------------------------------------------------------------------
// Fused projection GEMM: 512 tiles, all single-pass fp16
// ---------------------------------------------------------------------------
__global__ __launch_bounds__(256, 2) void proj_kernel(
    const float* __restrict__ bs,  const float* __restrict__ ba,
    const float* __restrict__ bts, const float* __restrict__ bta,
    const float* __restrict__ bv)
{
    const int t = blockIdx.x;
    if (t < 384) {
        const int mt = t / 6;
        const int nt = t % 6;
        const uint* B; const float* bias; int ldbw;
        switch (nt) {
            case 0:  B = g_Wsf;        bias = bs;        ldbw = 256; break;
            case 1:  B = g_Wsf + 128;  bias = bs + 128;  ldbw = 256; break;
            case 2:  B = g_Waf;        bias = ba;        ldbw = 128; break;
            case 3:  B = g_Wtsf;       bias = bts;       ldbw = 256; break;
            case 4:  B = g_Wtsf + 128; bias = bts + 128; ldbw = 256; break;
            default: B = g_Wtaf;       bias = bta;       ldbw = 128; break;
        }
        gemm_mma1<128, float>(g_qf16, B, ldbw, bias, g_proj + nt * 128, 768, mt);
    } else {
        const int u = t - 384;
        const int mt = u >> 1;
        const int nt = u & 1;
        gemm_mma1<128, __half>(g_if16, g_Wvf + nt * 128, 256,
                               bv + nt * 128, g_value_h + nt * 128, 256, mt);
    }
}

// Output GEMM: single-pass fp16, BM=64 -> grid 256
__global__ __launch_bounds__(256, 2) void out_kernel(
    const float* __restrict__ bo, float* __restrict__ out)
{
    const int mt = blockIdx.x >> 1;
    const int nt = blockIdx.x & 1;
    gemm_mma1<64, float>(g_of16, g_Wof + nt * 128, 256,
                         bo + nt * 128, out + nt * 128, 256, mt);
}

// ---------------------------------------------------------------------------
// Sampling kernel: one warp per (q, head).
// Accumulate: lane = pp(1b) x tap(2b) x c4(2b); one warp-LDG.128 covers
// 2 points x 4 taps x 16 B. Reduce via shfl-xor 4, 8, 16.
// ---------------------------------------------------------------------------
__global__ __launch_bounds__(256) void sample_kernel(
    const float* __restrict__ ref,
    const float* __restrict__ toff)
{
    __shared__ float2 s_rw[8][32][4];    // x = row (int bits), y = fused weight

    const int wid   = threadIdx.x >> 5;
    const int lane  = threadIdx.x & 31;
    const int q     = blockIdx.x;
    const int head  = wid;

    const float* prow = g_proj + (size_t)q * 768;

    // ---- setup: lane == point index p ----
    {
        const int p = lane;
        const int l = p >> 3;
        const int j = p & 7;
        const int W = 48 >> l;
        const int H = 128 >> l;
        const float Wl = (float)W;
        const float Hl = (float)H;

        const float refx = ref[q * 8 + l * 2 + 0];
        const float refy = ref[q * 8 + l * 2 + 1];

        float lg, lx, ly;
        if (j < 4) {
            lg = prow[256 + head * 16 + l * 4 + j];
            const float ox = prow[head * 32 + l * 8 + j * 2 + 0];
            const float oy = prow[head * 32 + l * 8 + j * 2 + 1];
            lx = refx + ox / Wl;
            ly = refy + oy / Hl;
        } else {
            const int kk = j - 4;
            const int tw = kk >> 1;
            lg = prow[640 + head * 16 + l * 4 + kk];
            const float ox = prow[384 + head * 32 + l * 8 + kk * 2 + 0];
            const float oy = prow[384 + head * 32 + l * 8 + kk * 2 + 1];
            const float tx = toff[q * 16 + l * 4 + tw * 2 + 0];
            const float ty = toff[q * 16 + l * 4 + tw * 2 + 1];
            lx = refx + tx + ox / Wl;
            ly = refy + ty + oy / Hl;
        }

        float m = lg;
        #pragma unroll
        for (int o = 16; o > 0; o >>= 1)
            m = fmaxf(m, __shfl_xor_sync(0xffffffffu, m, o));
        float e = expf(lg - m);
        float s = e;
        #pragma unroll
        for (int o = 16; o > 0; o >>= 1)
            s += __shfl_xor_sync(0xffffffffu, s, o);
        const float wgt = e / s;

        const float gx = lx * Wl - 0.5f;
        const float gy = ly * Hl - 0.5f;
        const float fx0 = floorf(gx), fy0 = floorf(gy);
        const int ix0 = (int)fx0, iy0 = (int)fy0;
        const int ix1 = ix0 + 1,  iy1 = iy0 + 1;
        const float wx = gx - fx0, wy = gy - fy0;

        const bool vx0 = (ix0 >= 0) & (ix0 < W);
        const bool vx1 = (ix1 >= 0) & (ix1 < W);
        const bool vy0 = (iy0 >= 0) & (iy0 < H);
        const bool vy1 = (iy1 >= 0) & (iy1 < H);

        const int cx0 = min(max(ix0, 0), W - 1);
        const int cx1 = min(max(ix1, 0), W - 1);
        const int cy0 = min(max(iy0, 0), H - 1);
        const int cy1 = min(max(iy1, 0), H - 1);

        const int st = c_lstart[l];
        s_rw[wid][p][0] = make_float2(
            __int_as_float(st + cy0 * W + cx0),
            (vx0 & vy0) ? wgt * (1.f - wx) * (1.f - wy) : 0.f);
        s_rw[wid][p][1] = make_float2(
            __int_as_float(st + cy0 * W + cx1),
            (vx1 & vy0) ? wgt * wx * (1.f - wy) : 0.f);
        s_rw[wid][p][2] = make_float2(
            __int_as_float(st + cy1 * W + cx0),
            (vx0 & vy1) ? wgt * (1.f - wx) * wy : 0.f);
        s_rw[wid][p][3] = make_float2(
            __int_as_float(st + cy1 * W + cx1),
            (vx1 & vy1) ? wgt * wx * wy : 0.f);
    }
    __syncwarp();

    // ---- accumulate: lane = pp*16 + tap*4 + c4; channels [8*c4, 8*c4+8) ----
    const int pp  = lane >> 4;
    const int tap = (lane >> 2) & 3;
    const int c4  = lane & 3;
    const __half* vbase = g_value_h + head * 32 + 8 * c4;

    float a0 = 0.f, a1 = 0.f, a2 = 0.f, a3 = 0.f;
    float a4 = 0.f, a5 = 0.f, a6 = 0.f, a7 = 0.f;
    #pragma unroll
    for (int i = 0; i < 16; i++) {
        const int p = 2 * i + pp;
        const float2 rw = s_rw[wid][p][tap];
        const int    r  = __float_as_int(rw.x);
        const float  w  = rw.y;
        const uint4  v  = *(const uint4*)(vbase + (size_t)r * 256);
        const float2 f0 = __half22float2(*(const __half2*)&v.x);
        const float2 f1 = __half22float2(*(const __half2*)&v.y);
        const float2 f2 = __half22float2(*(const __half2*)&v.z);
        const float2 f3 = __half22float2(*(const __half2*)&v.w);
        a0 = fmaf(w, f0.x, a0);  a1 = fmaf(w, f0.y, a1);
        a2 = fmaf(w, f1.x, a2);  a3 = fmaf(w, f1.y, a3);
        a4 = fmaf(w, f2.x, a4);  a5 = fmaf(w, f2.y, a5);
        a6 = fmaf(w, f3.x, a6);  a7 = fmaf(w, f3.y, a7);
    }

    // reduce across taps (xor 4, 8) then across point-halves (xor 16)
    #pragma unroll
    for (int o = 4; o <= 16; o <<= 1) {
        a0 += __shfl_xor_sync(0xffffffffu, a0, o);
        a1 += __shfl_xor_sync(0xffffffffu, a1, o);
        a2 += __shfl_xor_sync(0xffffffffu, a2, o);
        a3 += __shfl_xor_sync(0xffffffffu, a3, o);
        a4 += __shfl_xor_sync(0xffffffffu, a4, o);
        a5 += __shfl_xor_sync(0xffffffffu, a5, o);
        a6 += __shfl_xor_sync(0xffffffffu, a6, o);
        a7 += __shfl_xor_sync(0xffffffffu, a7, o);
    }

    if (lane < 4) {
        uint4 o;
        o.x = pack2h(a0, a1);
        o.y = pack2h(a2, a3);
        o.z = pack2h(a4, a5);
        o.w = pack2h(a6, a7);
        *(uint4*)&g_of16[q * 128 + head * 16 + 4 * c4] = o;
    }
}

// ---------------------------------------------------------------------------
// Launch
// ---------------------------------------------------------------------------
extern "C" void kernel_launch(void* const* d_in, const int* in_sizes, int n_in,
                              void* d_out, int out_size)
{
    const float* query = (const float*)d_in[0];
    const float* ref   = (const float*)d_in[1];
    const float* toff  = (const float*)d_in[2];
    const float* inp   = (const float*)d_in[3];
    const float* Wv  = (const float*)d_in[6];
    const float* bv  = (const float*)d_in[7];
    const float* Ws  = (const float*)d_in[8];
    const float* bs  = (const float*)d_in[9];
    const float* Wa  = (const float*)d_in[10];
    const float* ba  = (const float*)d_in[11];
    const float* Wts = (const float*)d_in[12];
    const float* bts = (const float*)d_in[13];
    const float* Wta = (const float*)d_in[14];
    const float* bta = (const float*)d_in[15];
    const float* Wo  = (const float*)d_in[16];
    const float* bo  = (const float*)d_in[17];

    const int smemP = 3 * (int)sizeof(GemmSmemH<128>);
    const int smemO = 3 * (int)sizeof(GemmSmemH<64>);
    cudaFuncSetAttribute(proj_kernel, cudaFuncAttributeMaxDynamicSharedMemorySize, smemP);
    cudaFuncSetAttribute(out_kernel,  cudaFuncAttributeMaxDynamicSharedMemorySize, smemO);

    prep_kernel<<<2200, 256>>>(query, inp, Ws, Wa, Wts, Wta, Wv, Wo);

    proj_kernel<<<512, 256, smemP>>>(bs, ba, bts, bta, bv);

    sample_kernel<<<LQ, 256>>>(ref, toff);

    out_kernel<<<256, 256, smemO>>>(bo, (float*)d_out);
}